// round 8
// baseline (speedup 1.0000x reference)
#include <cuda_runtime.h>
#include <math.h>

#define BATCH 64
#define NTOT  65536
#define DIM   1024
#define NSPLIT 16
#define GRID  296          // 2 CTAs per SM on 148 SMs (all co-resident)
#define SLAB  222          // ceil(NTOT / GRID); last slab = 46 rows
#define SLOTS 24           // max slabs a single segment can span (<=10 in practice)
#define READY_TARGET (NSPLIT + 1)   // 16 tile-reducers + 1 setup

// ---------------- device scratch (static, no allocation) ----------------
__device__ float  g_vpart[NSPLIT * BATCH * DIM];
__device__ float  g_v[BATCH * DIM];
__device__ int    g_seg_node_start[BATCH + 1];
__device__ float  g_part_m[BATCH * SLOTS];
__device__ float  g_part_z[BATCH * SLOTS];
__device__ float4 g_part_acc[BATCH * SLOTS * (DIM / 4)];
__device__ int    g_tile_done[NSPLIT];   // split-K arrivals; self-cleaning
__device__ int    g_seg_done[BATCH];     // per-segment slab arrivals; self-cleaning
__device__ int    g_ready;               // release counter; reset by last finisher
__device__ int    g_fin;                 // finish counter; self-cleaning

// packed f32x2 helpers (sm_103a FFMA2 — PTX-only)
#define FMA2(d, a, b, c) \
    asm("fma.rn.f32x2 %0, %1, %2, %3;" : "=l"(d) : "l"(a), "l"(b), "l"(c))
#define PACK2(out, lo, hi) \
    asm("mov.b64 %0, {%1, %2};" : "=l"(out) : "f"(lo), "f"(hi))

__global__ void __launch_bounds__(256, 2) fused_kernel(
    const float* __restrict__ mem,
    const float* __restrict__ dstate,
    const float* __restrict__ W,
    const int*   __restrict__ lens_raw,
    float*       __restrict__ out)
{
    __shared__ char  s_raw[32 * 1024];           // aliased: vproj dsh2 / phase1 s_acc
    __shared__ float s_m[8], s_z[8];
    __shared__ int   s_segstart[BATCH + 1];
    __shared__ int   s_flag;

    int t    = threadIdx.x;
    int warp = t >> 5;
    int lane = t & 31;
    int cta  = blockIdx.x;

    // ================= stage A: setup (CTA 295) =================
    if (cta == GRID - 1) {
        __shared__ int s_len[BATCH];
        if (t < BATCH) {
            const long long* lens64 = (const long long*)lens_raw;
            bool is64 = (lens_raw[1] == 0);   // int64 LE: high word of elem0 is 0
            s_len[t] = is64 ? (int)lens64[t] : lens_raw[t];
        }
        __syncthreads();
        if (t == 0) {
            int off = 0;
            for (int i = 0; i < BATCH; i++) { g_seg_node_start[i] = off; off += s_len[i]; }
            g_seg_node_start[BATCH] = off;
            __threadfence();
            atomicAdd(&g_ready, 1);           // release setup
        }
    }
    // ================= stage A: v projection (CTAs 0..255) =================
    else if (cta < 256) {
        unsigned long long (*dsh2)[64] = (unsigned long long (*)[64])s_raw;
        int mx = cta & 3, by = (cta >> 2) & 3, hz = cta >> 4;
        int m  = mx * 256 + t;
        int b0 = by * 16;
        int h0 = hz * 64;

        for (int i = t; i < 8 * 64; i += 256) {
            int p = i >> 6, hh = i & 63;
            float lo = dstate[(b0 + 2 * p)     * DIM + h0 + hh];
            float hi = dstate[(b0 + 2 * p + 1) * DIM + h0 + hh];
            unsigned long long pk; PACK2(pk, lo, hi);
            dsh2[p][hh] = pk;
        }
        __syncthreads();

        unsigned long long acc2[8];
#pragma unroll
        for (int i = 0; i < 8; i++) acc2[i] = 0ull;
#pragma unroll 4
        for (int hh = 0; hh < 64; hh++) {
            float w = W[(size_t)(h0 + hh) * DIM + m];
            unsigned long long w2; PACK2(w2, w, w);
#pragma unroll
            for (int i = 0; i < 8; i++) FMA2(acc2[i], dsh2[i][hh], w2, acc2[i]);
        }

        float* outp = g_vpart + (size_t)hz * (BATCH * DIM);
#pragma unroll
        for (int i = 0; i < 8; i++) {
            unsigned long long a = acc2[i];
            outp[(b0 + 2 * i)     * DIM + m] = __int_as_float((int)(a & 0xffffffffull));
            outp[(b0 + 2 * i + 1) * DIM + m] = __int_as_float((int)(a >> 32));
        }
        __threadfence();
        __syncthreads();
        if (t == 0)
            s_flag = (atomicAdd(&g_tile_done[by * 4 + mx], 1) == NSPLIT - 1) ? 1 : 0;
        __syncthreads();
        if (s_flag) {   // last z-split of this (mx,by) tile: reduce 16 partials -> g_v
            __threadfence();
            for (int i = t; i < 16 * 256; i += 256) {
                int bl = i >> 8, mm = i & 255;
                int b  = b0 + bl;
                int mc = mx * 256 + mm;
                float s = 0.f;
#pragma unroll
                for (int p = 0; p < NSPLIT; p++)
                    s += g_vpart[(size_t)p * BATCH * DIM + b * DIM + mc];
                g_v[b * DIM + mc] = s;
            }
            __threadfence();
            __syncthreads();
            if (t == 0) {
                g_tile_done[by * 4 + mx] = 0;     // self-clean
                atomicAdd(&g_ready, 1);            // release this tile
            }
        }
    }

    // ================= barrier: wait for v + seg table (all 296 co-resident) ====
    if (t == 0) {
        while (*(volatile int*)&g_ready < READY_TARGET) __nanosleep(64);
    }
    __syncthreads();
    __threadfence();   // acquire ordering for g_v / g_seg_node_start reads

    for (int i = t; i <= BATCH; i += 256) s_segstart[i] = g_seg_node_start[i];
    __syncthreads();

    // ================= stage B: slab-streamed online softmax =================
    float4 (*s_acc)[256] = (float4 (*)[256])s_raw;

    int row_lo = cta * SLAB;
    int row_hi = row_lo + SLAB;
    if (row_hi > NTOT) row_hi = NTOT;

    // first segment containing row_lo (linear scan over 64)
    int seg = 0;
    while (s_segstart[seg + 1] <= row_lo) seg++;

    int lo = row_lo;
    while (lo < row_hi) {
        int segend = s_segstart[seg + 1];
        int hi  = segend < row_hi ? segend : row_hi;
        int cnt = hi - lo;

        // v row for this segment (L2-hot), register-resident
        const float4* vp = (const float4*)(g_v + seg * DIM);
        float4 v[8];
#pragma unroll
        for (int j = 0; j < 8; j++) v[j] = vp[j * 32 + lane];

        float m = -INFINITY, z = 0.f;
        float4 acc[8];
#pragma unroll
        for (int j = 0; j < 8; j++) acc[j] = make_float4(0.f, 0.f, 0.f, 0.f);

        for (int i = warp; i < cnt; i += 8) {
            const float4* row = (const float4*)(mem + (size_t)(lo + i) * DIM);
            float4 r[8];
#pragma unroll
            for (int j = 0; j < 8; j++) r[j] = row[j * 32 + lane];

            float s = 0.f;
#pragma unroll
            for (int j = 0; j < 8; j++)
                s += r[j].x * v[j].x + r[j].y * v[j].y + r[j].z * v[j].z + r[j].w * v[j].w;
#pragma unroll
            for (int o = 16; o > 0; o >>= 1) s += __shfl_xor_sync(0xffffffffu, s, o);

            if (s > m) {
                float sc = __expf(m - s);   // exp(-inf)=0 handles first node
                z = z * sc + 1.f;
#pragma unroll
                for (int j = 0; j < 8; j++) {
                    acc[j].x = acc[j].x * sc + r[j].x;
                    acc[j].y = acc[j].y * sc + r[j].y;
                    acc[j].z = acc[j].z * sc + r[j].z;
                    acc[j].w = acc[j].w * sc + r[j].w;
                }
                m = s;
            } else {
                float w8 = __expf(s - m);
                z += w8;
#pragma unroll
                for (int j = 0; j < 8; j++) {
                    acc[j].x = fmaf(w8, r[j].x, acc[j].x);
                    acc[j].y = fmaf(w8, r[j].y, acc[j].y);
                    acc[j].z = fmaf(w8, r[j].z, acc[j].z);
                    acc[j].w = fmaf(w8, r[j].w, acc[j].w);
                }
            }
        }

        // combine 8 warp-local accumulators -> piece partial
#pragma unroll
        for (int j = 0; j < 8; j++) s_acc[warp][j * 32 + lane] = acc[j];
        if (lane == 0) { s_m[warp] = m; s_z[warp] = z; }
        __syncthreads();

        float m_b = -INFINITY;
#pragma unroll
        for (int w = 0; w < 8; w++) m_b = fmaxf(m_b, s_m[w]);

        float  z_b = 0.f;
        float4 a   = make_float4(0.f, 0.f, 0.f, 0.f);
#pragma unroll
        for (int w = 0; w < 8; w++) {
            float mw = s_m[w];
            float sc = (mw == -INFINITY) ? 0.f : __expf(mw - m_b);  // idle warp -> 0
            float4 aw = s_acc[w][t];
            a.x = fmaf(sc, aw.x, a.x);
            a.y = fmaf(sc, aw.y, a.y);
            a.z = fmaf(sc, aw.z, a.z);
            a.w = fmaf(sc, aw.w, a.w);
            z_b = fmaf(sc, s_z[w], z_b);
        }

        // deterministic partial slot: slab index relative to segment's first slab
        int segstart = s_segstart[seg];
        int slot     = cta - segstart / SLAB;
        int base     = seg * SLOTS + slot;
        g_part_acc[(size_t)base * (DIM / 4) + t] = a;
        if (t == 0) { g_part_m[base] = m_b; g_part_z[base] = z_b; }

        __threadfence();
        __syncthreads();
        int np = (segend - 1) / SLAB - segstart / SLAB + 1;   // pieces for this segment
        if (t == 0)
            s_flag = (atomicAdd(&g_seg_done[seg], 1) == np - 1) ? 1 : 0;
        __syncthreads();
        if (s_flag) {   // last slab of this segment: final combine + normalize
            __threadfence();
            int b0s = seg * SLOTS;
            float m_g = -INFINITY;
            for (int ci = 0; ci < np; ci++) m_g = fmaxf(m_g, g_part_m[b0s + ci]);

            float  zg = 0.f;
            float4 ag = make_float4(0.f, 0.f, 0.f, 0.f);
            for (int ci = 0; ci < np; ci++) {
                float sc = __expf(g_part_m[b0s + ci] - m_g);
                float4 p = g_part_acc[(size_t)(b0s + ci) * (DIM / 4) + t];
                ag.x = fmaf(sc, p.x, ag.x);
                ag.y = fmaf(sc, p.y, ag.y);
                ag.z = fmaf(sc, p.z, ag.z);
                ag.w = fmaf(sc, p.w, ag.w);
                zg = fmaf(sc, g_part_z[b0s + ci], zg);
            }
            float inv = 1.f / zg;
            ((float4*)out)[seg * (DIM / 4) + t] =
                make_float4(ag.x * inv, ag.y * inv, ag.z * inv, ag.w * inv);
            if (t == 0) g_seg_done[seg] = 0;   // self-clean
        }
        __syncthreads();   // protect shared before next piece

        lo = hi;
        seg++;
    }

    // ---- last CTA to finish resets the release counters for graph replay ----
    if (t == 0) {
        if (atomicAdd(&g_fin, 1) == GRID - 1) {
            g_ready = 0;
            g_fin   = 0;
        }
    }
}

// ---------------- launch ----------------
extern "C" void kernel_launch(void* const* d_in, const int* in_sizes, int n_in,
                              void* d_out, int out_size) {
    // Identify inputs by element count (ordering-proof):
    //   memory_bank 67108864, decoder_state 65536, W 1048576, lens 64.
    const float* mem    = nullptr;
    const float* dstate = nullptr;
    const float* W      = nullptr;
    const int*   lens   = nullptr;
    for (int i = 0; i < n_in; i++) {
        switch (in_sizes[i]) {
            case 67108864: mem    = (const float*)d_in[i]; break;
            case 65536:    dstate = (const float*)d_in[i]; break;
            case 1048576:  W      = (const float*)d_in[i]; break;
            case 64:       lens   = (const int*)d_in[i];   break;
        }
    }
    float* out = (float*)d_out;

    fused_kernel<<<GRID, 256>>>(mem, dstate, W, lens, out);
}